// round 2
// baseline (speedup 1.0000x reference)
#include <cuda_runtime.h>

#define NN 307
#define DD 64
#define EE 4912
#define TT 288
#define BB 8

// ---- scratch (device globals; no allocation allowed) ----
__device__ float g_h[2][NN * DD];   // ping-pong layer activations
__device__ float g_p[NN * DD];      // projected features p = h @ W
__device__ float g_ss[NN * 8];      // per-node src scores
__device__ float g_st[NN * 8];      // per-node tgt scores
__device__ float g_num[NN * DD];    // softmax-weighted numerator accum
__device__ float g_den[NN * 8];     // softmax denominator accum
__device__ float g_c[TT * DD];      // pe[t,d] + b_val[d]

// --------------------------------------------------------------------------
// Per-node kernel: (optionally compute nf), p = h @ W, ss/st scores, zero accums.
// grid = NN blocks, 64 threads.
// --------------------------------------------------------------------------
__global__ void k_node(const float* __restrict__ W,
                       const float* __restrict__ a_src,
                       const float* __restrict__ a_tgt,
                       int H, int F, int hbuf,
                       const float* __restrict__ node_features,  // non-null => layer0: build nf
                       const float* __restrict__ W_sta,
                       const float* __restrict__ b_sta,
                       const float* __restrict__ ada_emb)
{
    __shared__ float sh[DD];
    __shared__ float sp[DD];
    int n = blockIdx.x;
    int d = threadIdx.x;

    float hv;
    if (node_features) {
        float acc = b_sta[d] + ada_emb[n * DD + d];
#pragma unroll
        for (int k = 0; k < 32; k++)
            acc += node_features[n * 32 + k] * W_sta[k * DD + d];
        hv = acc;
        g_h[0][n * DD + d] = acc;   // keep nf for layer-0 skip path
    } else {
        hv = g_h[hbuf][n * DD + d];
    }
    sh[d] = hv;
    __syncthreads();

    float acc = 0.f;
#pragma unroll
    for (int k = 0; k < DD; k++)
        acc += sh[k] * W[k * DD + d];
    g_p[n * DD + d] = acc;
    g_num[n * DD + d] = 0.f;
    sp[d] = acc;
    __syncthreads();

    if (d < H) {
        float ssv = 0.f, stv = 0.f;
        for (int f = 0; f < F; f++) {
            float v = sp[d * F + f];
            ssv += v * a_src[d * F + f];
            stv += v * a_tgt[d * F + f];
        }
        g_ss[n * H + d] = ssv;
        g_st[n * H + d] = stv;
        g_den[n * H + d] = 0.f;
    }
}

// --------------------------------------------------------------------------
// Edge kernel: e = leaky_relu(ss[src]+st[tgt]); w = exp(e);
// num[tgt] += w * p[src]; den[tgt] += w.  (max-subtraction dropped: values are
// O(0.1) so exp cannot overflow; result is mathematically identical.)
// One thread per (edge, d) with d = h*F+f.
// --------------------------------------------------------------------------
__global__ void k_edge(const int* __restrict__ ei, int H, int F)
{
    int idx = blockIdx.x * blockDim.x + threadIdx.x;
    if (idx >= EE * DD) return;
    int e = idx >> 6;
    int d = idx & 63;
    int h = d / F;
    int f = d % F;
    int s = ei[e];
    int t = ei[EE + e];
    float ev = g_ss[s * H + h] + g_st[t * H + h];
    ev = ev > 0.f ? ev : 0.2f * ev;
    float w = __expf(ev);
    if (f == 0) atomicAdd(&g_den[t * H + h], w);
    atomicAdd(&g_num[t * DD + d], w * g_p[s * DD + d]);
}

// --------------------------------------------------------------------------
// Finalize: out = num/(den+eps) + skip + b; elu unless last. grid NN x 64.
// --------------------------------------------------------------------------
__global__ void k_fin(const float* __restrict__ skip_W,  // null => identity skip
                      const float* __restrict__ b,
                      int H, int F, int last, int inbuf, int outbuf)
{
    __shared__ float sh[DD];
    int n = blockIdx.x;
    int d = threadIdx.x;
    sh[d] = g_h[inbuf][n * DD + d];
    __syncthreads();

    float v = g_num[n * DD + d] / (g_den[n * H + d / F] + 1e-16f);
    float skip;
    if (skip_W) {
        skip = 0.f;
#pragma unroll
        for (int k = 0; k < DD; k++)
            skip += sh[k] * skip_W[k * DD + d];
    } else {
        skip = sh[d];
    }
    v += skip + b[d];
    if (!last) v = v > 0.f ? v : (expf(v) - 1.f);   // ELU, alpha=1
    g_h[outbuf][n * DD + d] = v;
}

// --------------------------------------------------------------------------
// c[t,d] = PE(t,d) + b_val[d]
// --------------------------------------------------------------------------
__global__ void k_ctab(const float* __restrict__ b_val)
{
    int idx = blockIdx.x * blockDim.x + threadIdx.x;
    if (idx >= TT * DD) return;
    int t = idx / DD;
    int d = idx % DD;
    // div_j = exp(2j * (-ln(10000)/64)), pe[t,2j]=sin(t*div_j), pe[t,2j+1]=cos
    float freq = expf((float)(d & ~1) * (-9.210340371976184f / 64.0f));
    float ang = (float)t * freq;
    float pe = (d & 1) ? cosf(ang) : sinf(ang);
    g_c[idx] = pe + b_val[d];
}

// --------------------------------------------------------------------------
// Big broadcast kernel: out[b,t,n,d] = x[b,t,n]*W_val[d] + c[t,d] + h[n,d]
// float4-vectorized: thread = (bt*N + n)*16 + dq, dq covers 4 d's.
// --------------------------------------------------------------------------
__global__ void k_big(const float* __restrict__ x,
                      const float* __restrict__ Wv,
                      float4* __restrict__ out, int total)
{
    int idx = blockIdx.x * blockDim.x + threadIdx.x;
    if (idx >= total) return;
    int dq = idx & 15;
    int rest = idx >> 4;            // (b*T + t)*N + n
    int n = rest % NN;
    int bt = rest / NN;
    int t = bt % TT;

    float xv = __ldg(&x[rest]);
    const float4 w  = ((const float4*)Wv)[dq];
    const float4 cc = ((const float4*)g_c)[t * 16 + dq];
    const float4 hh = ((const float4*)(g_h[1]))[n * 16 + dq];

    float4 o;
    o.x = fmaf(xv, w.x, cc.x + hh.x);
    o.y = fmaf(xv, w.y, cc.y + hh.y);
    o.z = fmaf(xv, w.z, cc.z + hh.z);
    o.w = fmaf(xv, w.w, cc.w + hh.w);
    out[idx] = o;
}

extern "C" void kernel_launch(void* const* d_in, const int* in_sizes, int n_in,
                              void* d_out, int out_size)
{
    const float* x       = (const float*)d_in[0];
    const float* node_f  = (const float*)d_in[1];
    const int*   ei      = (const int*)d_in[2];
    // d_in[3] edge_prob unused
    const float* W_val   = (const float*)d_in[4];
    const float* b_val   = (const float*)d_in[5];
    const float* W_sta   = (const float*)d_in[6];
    const float* b_sta   = (const float*)d_in[7];
    const float* ada     = (const float*)d_in[8];
    const float* g0W     = (const float*)d_in[9];
    const float* g0as    = (const float*)d_in[10];
    const float* g0at    = (const float*)d_in[11];
    const float* g0b     = (const float*)d_in[12];
    const float* g1W     = (const float*)d_in[13];
    const float* g1as    = (const float*)d_in[14];
    const float* g1at    = (const float*)d_in[15];
    const float* g1b     = (const float*)d_in[16];
    const float* g2W     = (const float*)d_in[17];
    const float* g2as    = (const float*)d_in[18];
    const float* g2at    = (const float*)d_in[19];
    const float* g2b     = (const float*)d_in[20];
    const float* g0skip  = (const float*)d_in[21];
    const float* g1skip  = (const float*)d_in[22];

    const int EB = (EE * DD + 255) / 256;

    // PE + bias table (independent of GAT chain)
    k_ctab<<<(TT * DD + 255) / 256, 256>>>(b_val);

    // Layer 0: nf -> buf0, finalize -> buf1
    k_node<<<NN, DD>>>(g0W, g0as, g0at, 8, 8, 0, node_f, W_sta, b_sta, ada);
    k_edge<<<EB, 256>>>(ei, 8, 8);
    k_fin<<<NN, DD>>>(g0skip, g0b, 8, 8, 0, 0, 1);

    // Layer 1: buf1 -> buf0
    k_node<<<NN, DD>>>(g1W, g1as, g1at, 8, 8, 1, nullptr, nullptr, nullptr, nullptr);
    k_edge<<<EB, 256>>>(ei, 8, 8);
    k_fin<<<NN, DD>>>(g1skip, g1b, 8, 8, 0, 1, 0);

    // Layer 2: buf0 -> buf1 (H=1, F=64, identity skip, no elu)
    k_node<<<NN, DD>>>(g2W, g2as, g2at, 1, 64, 0, nullptr, nullptr, nullptr, nullptr);
    k_edge<<<EB, 256>>>(ei, 1, 64);
    k_fin<<<NN, DD>>>(nullptr, g2b, 1, 64, 1, 0, 1);

    // Broadcast add (the only HBM-heavy kernel)
    int total = BB * TT * NN * 16;    // one thread per float4
    k_big<<<(total + 255) / 256, 256>>>(x, W_val, (float4*)d_out, total);
}